// round 5
// baseline (speedup 1.0000x reference)
#include <cuda_runtime.h>

#define DEPTH    512
#define NPAIR    255        // pairs 0..254 real; cols 510,511 zero PE
#define ROWS     64         // rows per block
#define THREADS  128        // 2 row-groups x 64 float4 columns (one depth half)
#define HALF4    64         // float4s per half (256 floats)
#define QH_N     32
#define QL_N     64

struct F2 { float x, y; };

// ---------------------------------------------------------------------------
// constexpr double-precision math (compile-time only)
// ---------------------------------------------------------------------------
constexpr double kTwoPiHi = 6.283185307179586;
constexpr double kTwoPiLo = 2.4492935982947064e-16;

constexpr double d_exp(double x) {          // x in [-9.3, 0]
    double y = x / 128.0;
    double t = 1.0 + y * (1.0 + y * (1.0/2 + y * (1.0/6 + y * (1.0/24 +
               y * (1.0/120 + y * (1.0/720 + y * (1.0/5040)))))));
    for (int i = 0; i < 7; ++i) t *= t;
    return t;
}
constexpr double d_reduce(double x) {       // x >= 0 -> [-pi, pi]
    long long n = (long long)(x / kTwoPiHi + 0.5);
    return (x - (double)n * kTwoPiHi) - (double)n * kTwoPiLo;
}
constexpr double d_sin(double x) {
    double r = d_reduce(x), r2 = r * r;
    double t = 1.0 - r2 / 342.0;
    t = 1.0 - r2 / 272.0 * t;
    t = 1.0 - r2 / 210.0 * t;
    t = 1.0 - r2 / 156.0 * t;
    t = 1.0 - r2 / 110.0 * t;
    t = 1.0 - r2 / 72.0  * t;
    t = 1.0 - r2 / 42.0  * t;
    t = 1.0 - r2 / 20.0  * t;
    t = 1.0 - r2 / 6.0   * t;
    return r * t;
}
constexpr double d_cos(double x) {
    double r = d_reduce(x), r2 = r * r;
    double t = 1.0 - r2 / 380.0;
    t = 1.0 - r2 / 306.0 * t;
    t = 1.0 - r2 / 240.0 * t;
    t = 1.0 - r2 / 182.0 * t;
    t = 1.0 - r2 / 132.0 * t;
    t = 1.0 - r2 / 90.0  * t;
    t = 1.0 - r2 / 56.0  * t;
    t = 1.0 - r2 / 30.0  * t;
    t = 1.0 - r2 / 12.0  * t;
    t = 1.0 - r2 / 2.0   * t;
    return t;
}

// phasor(M * w_j); TAILC = cos-component for j >= NPAIR (1 = identity, 0 = zero)
template<int M, int TAILC>
struct SeedGen {
    F2 v[256];
    constexpr SeedGen() : v() {
        for (int j = 0; j < 256; ++j) {
            if (j >= NPAIR) { v[j].x = 0.f; v[j].y = (float)TAILC; }
            else {
                double w = d_exp(-9.210340371976184 * (double)j / 256.0);
                double a = (double)M * w;
                v[j].x = (float)d_sin(a);
                v[j].y = (float)d_cos(a);
            }
        }
    }
};

__device__ const SeedGen<4096, 1> c_S4096{};   // T1 step (identity at 255)
__device__ const SeedGen<64,   1> c_S64{};     // T2 step (identity at 255)
__device__ const SeedGen<1,    0> c_S1{};      // Trow[1]  (zero at 255)
__device__ const SeedGen<2,    1> c_S2{};      // per-row step (identity at 255)

// Runtime tables (.x = sin, .y = cos), index [slot*256 + j]
__device__ float2 g_T1  [QH_N * 256];  // phasor(qh * 4096 * w_j)
__device__ float2 g_T2  [QL_N * 256];  // phasor(ql * 64   * w_j)
__device__ float2 g_Trow[2 * 256];     // phasor(tg * w_j), tg in {0,1}
__device__ float2 g_S2  [256];         // phasor(2 * w_j)

__device__ __forceinline__ float2 cmul(float2 a, float2 b)
{   // (sin,cos) angle addition
    return make_float2(fmaf(a.x, b.y,  a.y * b.x),
                       fmaf(a.y, b.y, -a.x * b.x));
}

// ---------------------------------------------------------------------------
// Init: 256 threads, thread j. Pure f32 recurrences off constexpr seeds.
// ---------------------------------------------------------------------------
__global__ void init_tables_kernel()
{
    const int j = threadIdx.x;

    float2 step1 = make_float2(c_S4096.v[j].x, c_S4096.v[j].y);
    float2 v = make_float2(0.f, 1.f);
    #pragma unroll 4
    for (int q = 0; q < QH_N; ++q) {
        g_T1[q * 256 + j] = v;
        v = cmul(v, step1);
    }

    float2 step2 = make_float2(c_S64.v[j].x, c_S64.v[j].y);
    v = make_float2(0.f, 1.f);
    #pragma unroll 4
    for (int q = 0; q < QL_N; ++q) {
        g_T2[q * 256 + j] = v;
        v = cmul(v, step2);
    }

    g_Trow[j]       = (j < NPAIR) ? make_float2(0.f, 1.f) : make_float2(0.f, 0.f);
    g_Trow[256 + j] = make_float2(c_S1.v[j].x, c_S1.v[j].y);
    g_S2[j]         = make_float2(c_S2.v[j].x, c_S2.v[j].y);
}

// ---------------------------------------------------------------------------
// Main: 1-D grid, halves-major: bid = h * nchunks + chunk.
// Block: 64 rows x one 256-col depth half. Per-SM wordlist footprint
// 203 KB -> L1-resident gathers.
// ---------------------------------------------------------------------------
__global__ __launch_bounds__(THREADS)
void emb_pe_kernel(const int* __restrict__ idx,
                   const float4* __restrict__ wl4,   // [VOCAB][128] float4
                   float4* __restrict__ out4,        // [L][128] float4
                   int L, int nchunks)
{
    __shared__ int sh_idx[ROWS];

    const int bid   = blockIdx.x;
    const int h     = (bid >= nchunks) ? 1 : 0;
    const int chunk = bid - h * nchunks;
    const int row0  = chunk * ROWS;
    const int nrows = min(ROWS, L - row0);
    const int tid   = threadIdx.x;

    if (tid < nrows) sh_idx[tid] = idx[row0 + tid];
    __syncthreads();

    const int tg = tid >> 6;          // 0 or 1: row parity within chunk
    const int c  = tid & 63;          // float4 column within half
    const int j0 = h * 128 + 2 * c;   // pair ids for this float4
    const int j1 = j0 + 1;
    const int qh = chunk >> 6;        // < 32
    const int ql = chunk & 63;

    // base phasor = T1[qh] * T2[ql] * Trow[tg]
    float2 P0 = cmul(cmul(g_T1[(qh << 8) + j0], g_T2[(ql << 8) + j0]),
                     g_Trow[(tg << 8) + j0]);
    float2 P1 = cmul(cmul(g_T1[(qh << 8) + j1], g_T2[(ql << 8) + j1]),
                     g_Trow[(tg << 8) + j1]);
    const float2 S0 = g_S2[j0];
    const float2 S1 = g_S2[j1];

    float s0 = P0.x, c0 = P0.y, s1 = P1.x, c1 = P1.y;

    const int colbase = h * HALF4 + c;
    float4* outp = out4 + (size_t)(row0 + tg) * (DEPTH / 4) + colbase;

    #pragma unroll 8
    for (int r = tg; r < nrows; r += 2) {
        int token = sh_idx[r];
        float4 e = __ldg(&wl4[token * (DEPTH / 4) + colbase]);
        float4 o;
        o.x = e.x + s0;
        o.y = e.y + c0;
        o.z = e.z + s1;
        o.w = e.w + c1;
        __stcs(outp, o);
        outp += 2 * (DEPTH / 4);

        float ns0 = fmaf(s0, S0.y,  c0 * S0.x);
        float nc0 = fmaf(c0, S0.y, -s0 * S0.x);
        float ns1 = fmaf(s1, S1.y,  c1 * S1.x);
        float nc1 = fmaf(c1, S1.y, -s1 * S1.x);
        s0 = ns0; c0 = nc0; s1 = ns1; c1 = nc1;
    }
}

extern "C" void kernel_launch(void* const* d_in, const int* in_sizes, int n_in,
                              void* d_out, int out_size)
{
    const int*   idx = (const int*)d_in[0];
    const float* wl  = (const float*)d_in[1];
    float*       out = (float*)d_out;

    int L       = in_sizes[0];
    int nchunks = (L + ROWS - 1) / ROWS;

    init_tables_kernel<<<1, 256>>>();

    emb_pe_kernel<<<2 * nchunks, THREADS>>>(idx, (const float4*)wl,
                                            (float4*)out, L, nchunks);
}

// round 6
// speedup vs baseline: 1.0942x; 1.0942x over previous
#include <cuda_runtime.h>

#define DEPTH    512
#define NPAIR    255        // pairs 0..254 real; cols 510,511 zero PE
#define ROWS     64         // rows per block
#define THREADS  128        // 2 row-groups x 64 float4 columns (one depth half)
#define HALF4    64         // float4s per half (256 floats)
#define QH_N     32
#define QL_N     64

struct F2 { float x, y; };

// ---------------------------------------------------------------------------
// constexpr double-precision math (compile-time only)
// ---------------------------------------------------------------------------
constexpr double kTwoPiHi = 6.283185307179586;
constexpr double kTwoPiLo = 2.4492935982947064e-16;

constexpr double d_exp(double x) {          // x in [-9.3, 0]
    double y = x / 128.0;
    double t = 1.0 + y * (1.0 + y * (1.0/2 + y * (1.0/6 + y * (1.0/24 +
               y * (1.0/120 + y * (1.0/720 + y * (1.0/5040)))))));
    for (int i = 0; i < 7; ++i) t *= t;
    return t;
}
constexpr double d_reduce(double x) {       // x >= 0 -> [-pi, pi]
    long long n = (long long)(x / kTwoPiHi + 0.5);
    return (x - (double)n * kTwoPiHi) - (double)n * kTwoPiLo;
}
constexpr double d_sin(double x) {
    double r = d_reduce(x), r2 = r * r;
    double t = 1.0 - r2 / 342.0;
    t = 1.0 - r2 / 272.0 * t;
    t = 1.0 - r2 / 210.0 * t;
    t = 1.0 - r2 / 156.0 * t;
    t = 1.0 - r2 / 110.0 * t;
    t = 1.0 - r2 / 72.0  * t;
    t = 1.0 - r2 / 42.0  * t;
    t = 1.0 - r2 / 20.0  * t;
    t = 1.0 - r2 / 6.0   * t;
    return r * t;
}
constexpr double d_cos(double x) {
    double r = d_reduce(x), r2 = r * r;
    double t = 1.0 - r2 / 380.0;
    t = 1.0 - r2 / 306.0 * t;
    t = 1.0 - r2 / 240.0 * t;
    t = 1.0 - r2 / 182.0 * t;
    t = 1.0 - r2 / 132.0 * t;
    t = 1.0 - r2 / 90.0  * t;
    t = 1.0 - r2 / 56.0  * t;
    t = 1.0 - r2 / 30.0  * t;
    t = 1.0 - r2 / 12.0  * t;
    t = 1.0 - r2 / 2.0   * t;
    return t;
}

// Table of phasor(q * STRIDE * w_j) for q in [0, COUNT), j in [0, 256).
// Entries with j >= NPAIR get (0, TAILC).
template<int STRIDE, int COUNT, int TAILC>
struct TableGen {
    F2 v[COUNT * 256];
    constexpr TableGen() : v() {
        for (int q = 0; q < COUNT; ++q) {
            for (int j = 0; j < 256; ++j) {
                F2& e = v[q * 256 + j];
                if (j >= NPAIR) { e.x = 0.f; e.y = (float)TAILC; }
                else {
                    double w = d_exp(-9.210340371976184 * (double)j / 256.0);
                    double a = (double)q * (double)STRIDE * w;
                    e.x = (float)d_sin(a);
                    e.y = (float)d_cos(a);
                }
            }
        }
    }
};

// Step table: phasor(2 * w_j); identity at tail so (0,0) phasors stay zero.
struct StepGen {
    F2 v[256];
    constexpr StepGen() : v() {
        for (int j = 0; j < 256; ++j) {
            if (j >= NPAIR) { v[j].x = 0.f; v[j].y = 1.f; }
            else {
                double w = d_exp(-9.210340371976184 * (double)j / 256.0);
                v[j].x = (float)d_sin(2.0 * w);
                v[j].y = (float)d_cos(2.0 * w);
            }
        }
    }
};

// All tables baked into the cubin at compile time — no init kernel.
__device__ const TableGen<4096, QH_N, 1> c_T1{};   // phasor(qh * 4096 * w_j)
__device__ const TableGen<64,   QL_N, 1> c_T2{};   // phasor(ql * 64   * w_j)
__device__ const TableGen<1,    2,    0> c_Trow{}; // phasor(tg * w_j); zero tail
__device__ const StepGen                 c_S2{};   // phasor(2 * w_j)

__device__ __forceinline__ float2 cmul(float2 a, float2 b)
{   // (sin,cos) angle addition
    return make_float2(fmaf(a.x, b.y,  a.y * b.x),
                       fmaf(a.y, b.y, -a.x * b.x));
}

__device__ __forceinline__ float2 ldF2(const F2* p)
{
    return *reinterpret_cast<const float2*>(p);
}

// ---------------------------------------------------------------------------
// Main: 1-D grid, halves-major: bid = h * nchunks + chunk.
// Block: 64 rows x one 256-col depth half. Per-SM wordlist footprint
// 203 KB -> L1-resident gathers.
// ---------------------------------------------------------------------------
__global__ __launch_bounds__(THREADS)
void emb_pe_kernel(const int* __restrict__ idx,
                   const float4* __restrict__ wl4,   // [VOCAB][128] float4
                   float4* __restrict__ out4,        // [L][128] float4
                   int L, int nchunks)
{
    __shared__ int sh_idx[ROWS];

    const int bid   = blockIdx.x;
    const int h     = (bid >= nchunks) ? 1 : 0;
    const int chunk = bid - h * nchunks;
    const int row0  = chunk * ROWS;
    const int nrows = min(ROWS, L - row0);
    const int tid   = threadIdx.x;

    if (tid < nrows) sh_idx[tid] = idx[row0 + tid];
    __syncthreads();

    const int tg = tid >> 6;          // 0 or 1: row parity within chunk
    const int c  = tid & 63;          // float4 column within half
    const int j0 = h * 128 + 2 * c;   // pair ids for this float4
    const int j1 = j0 + 1;
    const int qh = chunk >> 6;        // < 32
    const int ql = chunk & 63;

    // base phasor = T1[qh] * T2[ql] * Trow[tg]
    float2 P0 = cmul(cmul(ldF2(&c_T1.v[(qh << 8) + j0]),
                          ldF2(&c_T2.v[(ql << 8) + j0])),
                     ldF2(&c_Trow.v[(tg << 8) + j0]));
    float2 P1 = cmul(cmul(ldF2(&c_T1.v[(qh << 8) + j1]),
                          ldF2(&c_T2.v[(ql << 8) + j1])),
                     ldF2(&c_Trow.v[(tg << 8) + j1]));
    const float2 S0 = ldF2(&c_S2.v[j0]);
    const float2 S1 = ldF2(&c_S2.v[j1]);

    float s0 = P0.x, c0 = P0.y, s1 = P1.x, c1 = P1.y;

    const int colbase = h * HALF4 + c;
    float4* outp = out4 + (size_t)(row0 + tg) * (DEPTH / 4) + colbase;

    #pragma unroll 8
    for (int r = tg; r < nrows; r += 2) {
        int token = sh_idx[r];
        float4 e = __ldg(&wl4[token * (DEPTH / 4) + colbase]);
        float4 o;
        o.x = e.x + s0;
        o.y = e.y + c0;
        o.z = e.z + s1;
        o.w = e.w + c1;
        __stcs(outp, o);
        outp += 2 * (DEPTH / 4);

        float ns0 = fmaf(s0, S0.y,  c0 * S0.x);
        float nc0 = fmaf(c0, S0.y, -s0 * S0.x);
        float ns1 = fmaf(s1, S1.y,  c1 * S1.x);
        float nc1 = fmaf(c1, S1.y, -s1 * S1.x);
        s0 = ns0; c0 = nc0; s1 = ns1; c1 = nc1;
    }
}

extern "C" void kernel_launch(void* const* d_in, const int* in_sizes, int n_in,
                              void* d_out, int out_size)
{
    const int*   idx = (const int*)d_in[0];
    const float* wl  = (const float*)d_in[1];
    float*       out = (float*)d_out;

    int L       = in_sizes[0];
    int nchunks = (L + ROWS - 1) / ROWS;

    emb_pe_kernel<<<2 * nchunks, THREADS>>>(idx, (const float4*)wl,
                                            (float4*)out, L, nchunks);
}